// round 10
// baseline (speedup 1.0000x reference)
#include <cuda_runtime.h>

// Problem constants
#define N     6144
#define GRID  148
#define MAXR  48
// Kernel P (reduce): 512 threads, 12 j's/thread (6 packed pairs), K+V in regs.
#define TP    512
#define JP    12
// Kernel W (write): 1024 threads, 3 interleaved j-pairs/thread, K only.
#define TW    1024

typedef unsigned long long u64;

// MUFU.EX2 forced via PTX.
__device__ __forceinline__ float ex2(float v) {
    float r;
    asm("ex2.approx.f32 %0, %1;" : "=f"(r) : "f"(v));
    return r;
}
// Packed f32x2 ops (FFMA2/FADD2/FMUL2 — only reachable via PTX).
__device__ __forceinline__ u64 pk2(float lo, float hi) {
    u64 r; asm("mov.b64 %0, {%1,%2};" : "=l"(r) : "f"(lo), "f"(hi)); return r;
}
__device__ __forceinline__ void upk2(u64 v, float& lo, float& hi) {
    asm("mov.b64 {%0,%1}, %2;" : "=f"(lo), "=f"(hi) : "l"(v));
}
__device__ __forceinline__ u64 fma2_(u64 a, u64 b, u64 c) {
    u64 r; asm("fma.rn.f32x2 %0, %1, %2, %3;" : "=l"(r) : "l"(a), "l"(b), "l"(c)); return r;
}
__device__ __forceinline__ u64 mul2_(u64 a, u64 b) {
    u64 r; asm("mul.rn.f32x2 %0, %1, %2;" : "=l"(r) : "l"(a), "l"(b)); return r;
}
__device__ __forceinline__ u64 add2_(u64 a, u64 b) {
    u64 r; asm("add.rn.f32x2 %0, %1, %2;" : "=l"(r) : "l"(a), "l"(b)); return r;
}

// Per-row handoff P -> W: (g1x,g1y,g1z)*log2e in xyz, 1/rowsum in w.
__device__ float4 d_rowmeta[N];

struct SmemP {
    float sg[MAXR][3];       // current phase's g rows, pre-scaled by log2(e)
    float y2[MAXR][3];       // (a2 @ v2) rows from phase A
    float red[2][16][13];    // parity-buffered per-warp partials (12 used)
    float tot[2][12];        // parity-buffered block totals
    float sinv[2][3];        // parity-buffered 1/rowsum
};

// ---------------------------------------------------------------------------
// Kernel P: both matrices, reduction-only (no a1 writes).
//   Mainloop fully f32x2-packed along j: per packed pair per row
//   3x FFMA2 (logit) + 2x MUFU.EX2 + 1 pack + FADD2 (sum) + 3x FFMA2 (e.v).
//   3 rows/iter; parity-buffered two-barrier reduction.
// ---------------------------------------------------------------------------
__global__ void __launch_bounds__(TP, 1) reduce_kernel(
    const float* __restrict__ x,
    const float* __restrict__ wq1, const float* __restrict__ bq1,
    const float* __restrict__ wq2, const float* __restrict__ bq2,
    const float* __restrict__ wq3, const float* __restrict__ bq3,
    const float* __restrict__ wq4, const float* __restrict__ bq4,
    const float* __restrict__ wk1, const float* __restrict__ bk1,
    const float* __restrict__ wk2, const float* __restrict__ bk2,
    const float* __restrict__ wv1, const float* __restrict__ bv1,
    const float* __restrict__ wv2, const float* __restrict__ bv2,
    const float* __restrict__ wb,  const float* __restrict__ bb,
    float* __restrict__ b_out)     // [N, 3]
{
    __shared__ SmemP sm;

    const int t  = threadIdx.x;
    const int j0 = t * JP;
    const int r0 = (int)(((long long)N * blockIdx.x) / GRID);
    const int r1 = (int)(((long long)N * (blockIdx.x + 1)) / GRID);
    const int nr = r1 - r0;
    const float LOG2E = 1.4426950408889634f;

    // Packed K/V: element p holds (s=2p, s=2p+1).
    u64 kxp[6], kyp[6], kzp[6], vxp[6], vyp[6], vzp[6];

    #pragma unroll
    for (int phase = 0; phase < 2; phase++) {
        const float* wk = phase ? wk1 : wk2;  const float* bk = phase ? bk1 : bk2;
        const float* wv = phase ? wv1 : wv2;  const float* bv = phase ? bv1 : bv2;
        const float* wA = phase ? wq1 : wq3;  const float* bA = phase ? bq1 : bq3;
        const float* wB = phase ? wq2 : wq4;  const float* bB = phase ? bq2 : bq4;

        {   // reload x slice each phase (cheap; frees 36 regs across mainloop)
            float xs[3 * JP];
            const float4* xp = (const float4*)(x + 3 * j0);
            #pragma unroll
            for (int q = 0; q < (3 * JP) / 4; q++) {
                float4 f = xp[q];
                xs[4*q] = f.x; xs[4*q+1] = f.y; xs[4*q+2] = f.z; xs[4*q+3] = f.w;
            }
            #pragma unroll
            for (int p = 0; p < 6; p++) {
                float X0 = xs[6*p+0], X1 = xs[6*p+1], X2 = xs[6*p+2];
                float Y0 = xs[6*p+3], Y1 = xs[6*p+4], Y2 = xs[6*p+5];
                kxp[p] = pk2(bk[0] + wk[0]*X0 + wk[1]*X1 + wk[2]*X2,
                             bk[0] + wk[0]*Y0 + wk[1]*Y1 + wk[2]*Y2);
                kyp[p] = pk2(bk[1] + wk[3]*X0 + wk[4]*X1 + wk[5]*X2,
                             bk[1] + wk[3]*Y0 + wk[4]*Y1 + wk[5]*Y2);
                kzp[p] = pk2(bk[2] + wk[6]*X0 + wk[7]*X1 + wk[8]*X2,
                             bk[2] + wk[6]*Y0 + wk[7]*Y1 + wk[8]*Y2);
                vxp[p] = pk2(bv[0] + wv[0]*X0 + wv[1]*X1 + wv[2]*X2,
                             bv[0] + wv[0]*Y0 + wv[1]*Y1 + wv[2]*Y2);
                vyp[p] = pk2(bv[1] + wv[3]*X0 + wv[4]*X1 + wv[5]*X2,
                             bv[1] + wv[3]*Y0 + wv[4]*Y1 + wv[5]*Y2);
                vzp[p] = pk2(bv[2] + wv[6]*X0 + wv[7]*X1 + wv[8]*X2,
                             bv[2] + wv[6]*Y0 + wv[7]*Y1 + wv[8]*Y2);
            }
        }
        if (t < nr) {
            int i = r0 + t;
            float X0 = x[3*i], X1 = x[3*i+1], X2 = x[3*i+2];
            #pragma unroll
            for (int c = 0; c < 3; c++) {
                float v = (bA[c] + bB[c])
                        + (wA[c*3+0] + wB[c*3+0]) * X0
                        + (wA[c*3+1] + wB[c*3+1]) * X1
                        + (wA[c*3+2] + wB[c*3+2]) * X2;
                sm.sg[t][c] = v * LOG2E;
            }
        }
        __syncthreads();

        int par = 0;
        for (int ii = 0; ii < nr; ii += 3, par ^= 1) {
            int li[3];
            #pragma unroll
            for (int rr = 0; rr < 3; rr++) li[rr] = (ii + rr < nr) ? ii + rr : nr - 1;

            u64 gx[3], gy[3], gz[3];
            #pragma unroll
            for (int rr = 0; rr < 3; rr++) {
                float a0 = sm.sg[li[rr]][0];
                float a1 = sm.sg[li[rr]][1];
                float a2 = sm.sg[li[rr]][2];
                gx[rr] = pk2(a0, a0);
                gy[rr] = pk2(a1, a1);
                gz[rr] = pk2(a2, a2);
            }

            u64 asum[3], axx[3], ayy[3], azz[3];
            #pragma unroll
            for (int rr = 0; rr < 3; rr++) { asum[rr]=0; axx[rr]=0; ayy[rr]=0; azz[rr]=0; }

            #pragma unroll
            for (int p = 0; p < 6; p++) {
                #pragma unroll
                for (int rr = 0; rr < 3; rr++) {
                    u64 l2 = fma2_(gx[rr], kxp[p],
                             fma2_(gy[rr], kyp[p], mul2_(gz[rr], kzp[p])));
                    float l0, l1;  upk2(l2, l0, l1);
                    u64 e2 = pk2(ex2(l0), ex2(l1));
                    asum[rr] = add2_(asum[rr], e2);
                    axx[rr]  = fma2_(e2, vxp[p], axx[rr]);
                    ayy[rr]  = fma2_(e2, vyp[p], ayy[rr]);
                    azz[rr]  = fma2_(e2, vzp[p], azz[rr]);
                }
            }

            float r[12];
            #pragma unroll
            for (int rr = 0; rr < 3; rr++) {
                float lo, hi;
                upk2(asum[rr], lo, hi); r[4*rr+0] = lo + hi;
                upk2(axx[rr],  lo, hi); r[4*rr+1] = lo + hi;
                upk2(ayy[rr],  lo, hi); r[4*rr+2] = lo + hi;
                upk2(azz[rr],  lo, hi); r[4*rr+3] = lo + hi;
            }
            #pragma unroll
            for (int o = 16; o > 0; o >>= 1) {
                #pragma unroll
                for (int q = 0; q < 12; q++)
                    r[q] += __shfl_xor_sync(0xffffffffu, r[q], o);
            }
            if ((t & 31) == 0) {
                int w = t >> 5;
                #pragma unroll
                for (int q = 0; q < 12; q++) sm.red[par][w][q] = r[q];
            }
            __syncthreads();
            if (t < 12 * 32) {   // stage 2: warp q reduces 16 per-warp partials
                int q = t >> 5, w = t & 31;
                float v = (w < 16) ? sm.red[par][w][q] : 0.f;
                #pragma unroll
                for (int o = 8; o > 0; o >>= 1)
                    v += __shfl_xor_sync(0xffffffffu, v, o);
                if (w == 0) {
                    sm.tot[par][q] = v;
                    if (q == 0) sm.sinv[par][0] = 1.0f / v;
                    if (q == 4) sm.sinv[par][1] = 1.0f / v;
                    if (q == 8) sm.sinv[par][2] = 1.0f / v;
                }
            }
            __syncthreads();

            if ((t & 31) == 0 && (t >> 5) < 3) {
                int rr = t >> 5;
                if (ii + rr < nr) {
                    float inv = sm.sinv[par][rr];
                    if (phase == 0) {
                        sm.y2[ii+rr][0] = sm.tot[par][4*rr+1] * inv;
                        sm.y2[ii+rr][1] = sm.tot[par][4*rr+2] * inv;
                        sm.y2[ii+rr][2] = sm.tot[par][4*rr+3] * inv;
                    } else {
                        int i = r0 + ii + rr;
                        float4 m;
                        m.x = sm.sg[ii+rr][0];
                        m.y = sm.sg[ii+rr][1];
                        m.z = sm.sg[ii+rr][2];
                        m.w = inv;
                        d_rowmeta[i] = m;
                        float y0 = sm.tot[par][4*rr+1] * inv + sm.y2[ii+rr][0];
                        float y1 = sm.tot[par][4*rr+2] * inv + sm.y2[ii+rr][1];
                        float y2 = sm.tot[par][4*rr+3] * inv + sm.y2[ii+rr][2];
                        #pragma unroll
                        for (int c = 0; c < 3; c++)
                            b_out[i*3+c] = bb[c] + wb[c*3+0]*y0
                                                 + wb[c*3+1]*y1
                                                 + wb[c*3+2]*y2;
                    }
                }
            }
            // no trailing barrier — next iter uses the other parity buffers
        }
        __syncthreads();   // phase A sg/y2 reads complete before phase B refills
    }
}

// ---------------------------------------------------------------------------
// Kernel W: streaming a1 writer. Zero smem / shfl / barriers.
//   Interleaved ownership (lane-consecutive 8B stores = perfect 128B
//   wavefronts). Packed f32x2 logits + scale; __stcs evict-first stream.
// ---------------------------------------------------------------------------
__global__ void __launch_bounds__(TW, 1) write_kernel(
    const float* __restrict__ x,
    const float* __restrict__ wk1, const float* __restrict__ bk1,
    float* __restrict__ a_out)     // [N, N]
{
    const int t  = threadIdx.x;
    const int r0 = (int)(((long long)N * blockIdx.x) / GRID);
    const int r1 = (int)(((long long)N * (blockIdx.x + 1)) / GRID);
    const int nr = r1 - r0;

    // Packed K1 for owned j-pairs: j = 2t + s*2048 + {0,1}, s = 0..2.
    u64 kxp[3], kyp[3], kzp[3];
    #pragma unroll
    for (int s = 0; s < 3; s++) {
        int j = 2 * t + s * 2048;
        float X0 = x[3*j+0], X1 = x[3*j+1], X2 = x[3*j+2];
        float Y0 = x[3*j+3], Y1 = x[3*j+4], Y2 = x[3*j+5];
        kxp[s] = pk2(bk1[0] + wk1[0]*X0 + wk1[1]*X1 + wk1[2]*X2,
                     bk1[0] + wk1[0]*Y0 + wk1[1]*Y1 + wk1[2]*Y2);
        kyp[s] = pk2(bk1[1] + wk1[3]*X0 + wk1[4]*X1 + wk1[5]*X2,
                     bk1[1] + wk1[3]*Y0 + wk1[4]*Y1 + wk1[5]*Y2);
        kzp[s] = pk2(bk1[2] + wk1[6]*X0 + wk1[7]*X1 + wk1[8]*X2,
                     bk1[2] + wk1[6]*Y0 + wk1[7]*Y1 + wk1[8]*Y2);
    }

    for (int ii = 0; ii < nr; ii += 4) {
        float4 m[4];
        int    iv[4];
        #pragma unroll
        for (int rr = 0; rr < 4; rr++) {
            int l = (ii + rr < nr) ? ii + rr : nr - 1;   // clamp (benign dup)
            iv[rr] = r0 + l;
            m[rr]  = d_rowmeta[iv[rr]];                  // broadcast LDG
        }
        #pragma unroll
        for (int rr = 0; rr < 4; rr++) {
            const u64 gx = pk2(m[rr].x, m[rr].x);
            const u64 gy = pk2(m[rr].y, m[rr].y);
            const u64 gz = pk2(m[rr].z, m[rr].z);
            const u64 iv2 = pk2(m[rr].w, m[rr].w);
            float* rowp = a_out + (size_t)iv[rr] * N + 2 * t;
            #pragma unroll
            for (int s = 0; s < 3; s++) {
                u64 l2 = fma2_(gx, kxp[s], fma2_(gy, kyp[s], mul2_(gz, kzp[s])));
                float l0, l1;  upk2(l2, l0, l1);
                u64 o2 = mul2_(pk2(ex2(l0), ex2(l1)), iv2);
                float2 o;  upk2(o2, o.x, o.y);
                __stcs((float2*)(rowp + s * 2048), o);   // evict-first stream
            }
        }
    }
}

// ---------------------------------------------------------------------------
// Two launches: reduce (y2, b, rowmeta) -> write (a1).
// Output layout: a1 [N*N] followed by b [N*3].
// ---------------------------------------------------------------------------
extern "C" void kernel_launch(void* const* d_in, const int* in_sizes, int n_in,
                              void* d_out, int out_size)
{
    const float* x   = (const float*)d_in[0];
    const float* wq1 = (const float*)d_in[1];
    const float* bq1 = (const float*)d_in[2];
    const float* wq2 = (const float*)d_in[3];
    const float* bq2 = (const float*)d_in[4];
    const float* wq3 = (const float*)d_in[5];
    const float* bq3 = (const float*)d_in[6];
    const float* wq4 = (const float*)d_in[7];
    const float* bq4 = (const float*)d_in[8];
    const float* wk1 = (const float*)d_in[9];
    const float* bk1 = (const float*)d_in[10];
    const float* wk2 = (const float*)d_in[11];
    const float* bk2 = (const float*)d_in[12];
    const float* wv1 = (const float*)d_in[13];
    const float* bv1 = (const float*)d_in[14];
    const float* wv2 = (const float*)d_in[15];
    const float* bv2 = (const float*)d_in[16];
    const float* wb  = (const float*)d_in[17];
    const float* bb  = (const float*)d_in[18];

    float* out = (float*)d_out;
    float* a1  = out;                      // [N, N]
    float* b   = out + (size_t)N * N;      // [N, 3]

    reduce_kernel<<<GRID, TP>>>(
        x, wq1, bq1, wq2, bq2, wq3, bq3, wq4, bq4,
        wk1, bk1, wk2, bk2, wv1, bv1, wv2, bv2,
        wb, bb, b);

    write_kernel<<<GRID, TW>>>(x, wk1, bk1, a1);
}